// round 12
// baseline (speedup 1.0000x reference)
#include <cuda_runtime.h>
#include <cuda_bf16.h>
#include <cuda_fp16.h>
#include <cstdint>

// ---------------------------------------------------------------------------
// SelfAttention B=8 N=2048 D=1024 ATT=128
//   FG: bf16 hi/lo 3-term split GEMM (fp32-equiv), CTA 128x256, 1 wave
//   fused attn: single-pass exact flash softmax -> P fp16 (unnormalized,
//     running max), ratio table, g_inv
//   AV: fp16 GEMM, CTA 128x128, 1024 threads (8 warps/SMSP), warp 16x32,
//     4 stages; flash ratio rescale + g_inv + residual.
// mma.sync + ldmatrix.x4 (tcgen05 unavailable in this harness toolchain).
// ---------------------------------------------------------------------------

#define BATCH 8
#define SEQ   2048
#define DIM   1024
#define BN_ROWS (BATCH*SEQ)

#define NT 512
#define NT2 1024

#define PITCH 80
#define ARR_128 (128*PITCH)            // 10240
#define ARR_256 (256*PITCH)            // 20480
#define FG_STAGE (2*ARR_128 + 2*ARR_256)   // 61440
#define FG_SMEM  (2*FG_STAGE)              // 122880
#define AV_STAGE (2*ARR_128)               // 20480
#define AV_STAGES 4
#define AV_SMEM (AV_STAGES*AV_STAGE)       // 81920
#define FPITCH 272
#define FARR (128*FPITCH)                  // 34816
#define GOFF0 (2*FARR)
#define REDOFF (6*FARR)                    // 208896
#define FUSED_SMEM (REDOFF + 4096)

// ------------------------------- scratch ----------------------------------
__device__ __nv_bfloat16 g_xh[BN_ROWS * DIM];
__device__ __nv_bfloat16 g_xl[BN_ROWS * DIM];
__device__ __half        g_xt[(size_t)BATCH * DIM * SEQ];
__device__ __nv_bfloat16 g_wth[256 * DIM];
__device__ __nv_bfloat16 g_wtl[256 * DIM];
__device__ float         g_biasc[256];
__device__ __nv_bfloat16 g_fgh[BN_ROWS * 256];
__device__ __nv_bfloat16 g_fgl[BN_ROWS * 256];
__device__ __half        g_p[(size_t)BATCH * SEQ * SEQ];   // exp(s - m_running)
__device__ float         g_ratio[(size_t)BN_ROWS * 16];    // per (row, tile)
__device__ float         g_inv[BN_ROWS];                   // 1 / Z

// ------------------------------- helpers ----------------------------------
__device__ __forceinline__ uint32_t smem_u32(const void* p) {
    uint32_t a;
    asm("{ .reg .u64 t; cvta.to.shared.u64 t, %1; cvt.u32.u64 %0, t; }"
        : "=r"(a) : "l"(p));
    return a;
}
__device__ __forceinline__ void mma_bf16(float* c, const uint32_t* a, const uint32_t* b) {
    asm volatile(
        "mma.sync.aligned.m16n8k16.row.col.f32.bf16.bf16.f32 "
        "{%0,%1,%2,%3},{%4,%5,%6,%7},{%8,%9},{%0,%1,%2,%3};\n"
        : "+f"(c[0]), "+f"(c[1]), "+f"(c[2]), "+f"(c[3])
        : "r"(a[0]), "r"(a[1]), "r"(a[2]), "r"(a[3]), "r"(b[0]), "r"(b[1]));
}
__device__ __forceinline__ void mma_f16(float* c, const uint32_t* a, const uint32_t* b) {
    asm volatile(
        "mma.sync.aligned.m16n8k16.row.col.f32.f16.f16.f32 "
        "{%0,%1,%2,%3},{%4,%5,%6,%7},{%8,%9},{%0,%1,%2,%3};\n"
        : "+f"(c[0]), "+f"(c[1]), "+f"(c[2]), "+f"(c[3])
        : "r"(a[0]), "r"(a[1]), "r"(a[2]), "r"(a[3]), "r"(b[0]), "r"(b[1]));
}
__device__ __forceinline__ void ldsm_x4(uint32_t* r, uint32_t addr) {
    asm volatile("ldmatrix.sync.aligned.m8n8.x4.shared.b16 {%0,%1,%2,%3}, [%4];"
        : "=r"(r[0]), "=r"(r[1]), "=r"(r[2]), "=r"(r[3]) : "r"(addr));
}
__device__ __forceinline__ void cp16(void* dst, const void* src) {
    uint32_t d = (uint32_t)__cvta_generic_to_shared(dst);
    asm volatile("cp.async.cg.shared.global [%0], [%1], 16;" :: "r"(d), "l"(src));
}
#define CP_COMMIT() asm volatile("cp.async.commit_group;" ::: "memory")
#define CP_WAIT(n)  asm volatile("cp.async.wait_group %0;" :: "n"(n) : "memory")

__device__ __forceinline__ void split_store(float v, __nv_bfloat16* h, __nv_bfloat16* l) {
    __nv_bfloat16 hi = __float2bfloat16(v);
    *h = hi;
    *l = __float2bfloat16(v - __bfloat162float(hi));
}

// ------------------------------ prep kernels ------------------------------
__global__ void prep_x_kernel(const float* __restrict__ x) {
    __shared__ float tile[32][33];
    int b = blockIdx.z;
    int n0 = blockIdx.x * 32, d0 = blockIdx.y * 32;
    int tx = threadIdx.x, ty = threadIdx.y;
    const float* xb = x + (size_t)b * SEQ * DIM;
#pragma unroll
    for (int j = 0; j < 4; j++) {
        int n = n0 + ty + 8 * j;
        float v = xb[(size_t)n * DIM + d0 + tx];
        tile[ty + 8 * j][tx] = v;
        size_t o = ((size_t)b * SEQ + n) * DIM + d0 + tx;
        split_store(v, &g_xh[o], &g_xl[o]);
    }
    __syncthreads();
    size_t base = (size_t)b * DIM * SEQ;
#pragma unroll
    for (int j = 0; j < 4; j++) {
        float v = tile[tx][ty + 8 * j];
        g_xt[base + (size_t)(d0 + ty + 8 * j) * SEQ + n0 + tx] = __float2half(v);
    }
}

__global__ void split_w_kernel(const float* __restrict__ Wf, const float* __restrict__ Wg,
                               const float* __restrict__ bfp, const float* __restrict__ bgp) {
    int idx = blockIdx.x * blockDim.x + threadIdx.x;
    if (idx < 256) g_biasc[idx] = (idx < 128) ? bfp[idx] : bgp[idx - 128];
    if (idx >= 256 * DIM) return;
    int n = idx >> 10;
    int k = idx & 1023;
    float v = (n < 128) ? Wf[(size_t)k * 128 + n] : Wg[(size_t)k * 128 + (n - 128)];
    split_store(v, &g_wth[idx], &g_wtl[idx]);
}

// --------------------- FG: bf16 split GEMM, CTA 128x256 -------------------
__global__ __launch_bounds__(NT)
void fg_gemm_kernel(const __nv_bfloat16* __restrict__ Ah, const __nv_bfloat16* __restrict__ Al,
                    const __nv_bfloat16* __restrict__ Bh, const __nv_bfloat16* __restrict__ Bl)
{
    extern __shared__ char smem[];
    const uint32_t sb = smem_u32(smem);
    const int tid = threadIdx.x;
    const int wid = tid >> 5;
    const int lane = tid & 31;
    const int m0 = blockIdx.x * 128;
    const int gq   = lane >> 2;
    const int tg2  = (lane & 3) * 2;
    const int rm   = (wid & 1) * 64;
    const int cn   = (wid >> 1) * 32;

    const uint32_t aoff = (uint32_t)(rm + (lane & 15)) * PITCH + (uint32_t)(lane >> 4) * 16;
    const uint32_t boff = (uint32_t)(cn + (lane & 7) + ((lane >> 4) & 1) * 8) * PITCH
                        + (uint32_t)((lane >> 3) & 1) * 16;

    const __nv_bfloat16* Arow_h = Ah + (size_t)m0 * DIM;
    const __nv_bfloat16* Arow_l = Al + (size_t)m0 * DIM;

    const int lrow = tid >> 2;
    const int lcc  = (tid & 3) * 16;

    float acc[4][4][4];
#pragma unroll
    for (int i = 0; i < 4; i++)
#pragma unroll
        for (int j = 0; j < 4; j++)
#pragma unroll
            for (int e = 0; e < 4; e++) acc[i][j][e] = 0.f;

    auto load_stage = [&](int s, int t) {
        const int k0 = t * 32;
        char* st = smem + s * FG_STAGE;
        uint32_t doff = (uint32_t)lrow * PITCH + lcc;
        cp16(st + doff,           (const char*)(Arow_h + (size_t)lrow * DIM + k0) + lcc);
        cp16(st + ARR_128 + doff, (const char*)(Arow_l + (size_t)lrow * DIM + k0) + lcc);
#pragma unroll
        for (int i = 0; i < 2; i++) {
            int brow = lrow + i * 128;
            uint32_t bo = (uint32_t)brow * PITCH + lcc;
            cp16(st + 2 * ARR_128 + bo,
                 (const char*)(Bh + (size_t)brow * DIM + k0) + lcc);
            cp16(st + 2 * ARR_128 + ARR_256 + bo,
                 (const char*)(Bl + (size_t)brow * DIM + k0) + lcc);
        }
    };

    load_stage(0, 0); CP_COMMIT();
    load_stage(1, 1); CP_COMMIT();

    const int T = DIM / 32;
    for (int t = 0; t < T; t++) {
        CP_WAIT(1);
        __syncthreads();
        const uint32_t stA = sb + (t & 1) * FG_STAGE;
        const uint32_t stB = stA + 2 * ARR_128;
#pragma unroll
        for (int ks = 0; ks < 32; ks += 16) {
            uint32_t ah[4][4], al[4][4], bh[4][2], bl[4][2];
#pragma unroll
            for (int mi = 0; mi < 4; mi++) {
                ldsm_x4(ah[mi], stA + aoff + mi * (16 * PITCH) + ks * 2);
                ldsm_x4(al[mi], stA + ARR_128 + aoff + mi * (16 * PITCH) + ks * 2);
            }
#pragma unroll
            for (int pr = 0; pr < 2; pr++) {
                uint32_t t4[4];
                ldsm_x4(t4, stB + boff + pr * (16 * PITCH) + ks * 2);
                bh[2 * pr][0] = t4[0]; bh[2 * pr][1] = t4[1];
                bh[2 * pr + 1][0] = t4[2]; bh[2 * pr + 1][1] = t4[3];
                ldsm_x4(t4, stB + ARR_256 + boff + pr * (16 * PITCH) + ks * 2);
                bl[2 * pr][0] = t4[0]; bl[2 * pr][1] = t4[1];
                bl[2 * pr + 1][0] = t4[2]; bl[2 * pr + 1][1] = t4[3];
            }
#pragma unroll
            for (int mi = 0; mi < 4; mi++)
#pragma unroll
                for (int ni = 0; ni < 4; ni++)
                    mma_bf16(acc[mi][ni], ah[mi], bh[ni]);
#pragma unroll
            for (int mi = 0; mi < 4; mi++)
#pragma unroll
                for (int ni = 0; ni < 4; ni++)
                    mma_bf16(acc[mi][ni], ah[mi], bl[ni]);
#pragma unroll
            for (int mi = 0; mi < 4; mi++)
#pragma unroll
                for (int ni = 0; ni < 4; ni++)
                    mma_bf16(acc[mi][ni], al[mi], bh[ni]);
        }
        __syncthreads();
        if (t + 2 < T) load_stage(t & 1, t + 2);
        CP_COMMIT();
    }

#pragma unroll
    for (int mi = 0; mi < 4; mi++)
#pragma unroll
        for (int ni = 0; ni < 4; ni++) {
            int r0 = m0 + rm + mi * 16 + gq;
            int c0 = cn + ni * 8 + tg2;
#pragma unroll
            for (int e = 0; e < 4; e++) {
                int r = r0 + (e >> 1) * 8;
                int c = c0 + (e & 1);
                float v = acc[mi][ni][e] + g_biasc[c];
                split_store(v, &g_fgh[(size_t)r * 256 + c], &g_fgl[(size_t)r * 256 + c]);
            }
        }
}

// ------------- fused attn: single-pass flash, ratio table ------------------
__global__ __launch_bounds__(NT)
void fused_attn_kernel()
{
    extern __shared__ char smem[];
    const uint32_t sb = smem_u32(smem);
    float* redBase = (float*)(smem + REDOFF);   // 2 x 512 floats

    const int tid = threadIdx.x;
    const int wid = tid >> 5;
    const int lane = tid & 31;
    const int gq   = lane >> 2;
    const int tg2  = (lane & 3) * 2;
    const int rm   = (wid & 3) * 32;
    const int cn   = (wid >> 2) * 32;
    const int m0 = blockIdx.x * 128;
    const int b  = blockIdx.y;
    const int grp = wid >> 2;          // n-warp-group 0..3

    const uint32_t aoff = (uint32_t)(rm + (lane & 15)) * FPITCH + (uint32_t)(lane >> 4) * 16;
    const uint32_t boff = (uint32_t)(cn + (lane & 7) + ((lane >> 4) & 1) * 8) * FPITCH
                        + (uint32_t)((lane >> 3) & 1) * 16;

    const size_t rowbase = (size_t)b * SEQ;

#pragma unroll
    for (int i = 0; i < 4; i++) {
        int idx = tid + i * NT;
        int row = idx >> 4;
        int c = (idx & 15) * 16;
        char* dst = smem + row * FPITCH + c;
        cp16(dst,        (const char*)(g_fgh + (rowbase + m0 + row) * 256) + c);
        cp16(dst + FARR, (const char*)(g_fgl + (rowbase + m0 + row) * 256) + c);
    }
    auto load_g = [&](int s, int nt) {
        char* st = smem + GOFF0 + s * (2 * FARR);
#pragma unroll
        for (int i = 0; i < 4; i++) {
            int idx = tid + i * NT;
            int row = idx >> 4;
            int c = (idx & 15) * 16;
            char* dst = st + row * FPITCH + c;
            cp16(dst,        (const char*)(g_fgh + (rowbase + nt * 128 + row) * 256 + 128) + c);
            cp16(dst + FARR, (const char*)(g_fgl + (rowbase + nt * 128 + row) * 256 + 128) + c);
        }
    };

    load_g(0, 0);
    CP_COMMIT();
    load_g(1, 1);
    CP_COMMIT();

    float m_run[2][2] = {{-1e30f, -1e30f}, {-1e30f, -1e30f}};
    float s_run[2][2] = {{0.f, 0.f}, {0.f, 0.f}};

    for (int nt = 0; nt < 16; nt++) {
        CP_WAIT(1);
        __syncthreads();
        const uint32_t stG = sb + GOFF0 + (nt & 1) * (2 * FARR);
        float* rS = redBase + (nt & 1) * 512;

        float acc[2][4][4];
#pragma unroll
        for (int i = 0; i < 2; i++)
#pragma unroll
            for (int j = 0; j < 4; j++)
#pragma unroll
                for (int e = 0; e < 4; e++) acc[i][j][e] = 0.f;

#pragma unroll
        for (int ksb = 0; ksb < 8; ksb++) {
            const int ks = ksb * 16;
            uint32_t ah[2][4], al[2][4], bh[4][2], bl[4][2];
#pragma unroll
            for (int mi = 0; mi < 2; mi++) {
                ldsm_x4(ah[mi], sb + aoff + mi * (16 * FPITCH) + ks * 2);
                ldsm_x4(al[mi], sb + FARR + aoff + mi * (16 * FPITCH) + ks * 2);
            }
#pragma unroll
            for (int pr = 0; pr < 2; pr++) {
                uint32_t t4[4];
                ldsm_x4(t4, stG + boff + pr * (16 * FPITCH) + ks * 2);
                bh[2 * pr][0] = t4[0]; bh[2 * pr][1] = t4[1];
                bh[2 * pr + 1][0] = t4[2]; bh[2 * pr + 1][1] = t4[3];
                ldsm_x4(t4, stG + FARR + boff + pr * (16 * FPITCH) + ks * 2);
                bl[2 * pr][0] = t4[0]; bl[2 * pr][1] = t4[1];
                bl[2 * pr + 1][0] = t4[2]; bl[2 * pr + 1][1] = t4[3];
            }
#pragma unroll
            for (int mi = 0; mi < 2; mi++)
#pragma unroll
                for (int ni = 0; ni < 4; ni++)
                    mma_bf16(acc[mi][ni], ah[mi], bh[ni]);
#pragma unroll
            for (int mi = 0; mi < 2; mi++)
#pragma unroll
                for (int ni = 0; ni < 4; ni++)
                    mma_bf16(acc[mi][ni], ah[mi], bl[ni]);
#pragma unroll
            for (int mi = 0; mi < 2; mi++)
#pragma unroll
                for (int ni = 0; ni < 4; ni++)
                    mma_bf16(acc[mi][ni], al[mi], bh[ni]);
        }

        float tmax[2][2];
#pragma unroll
        for (int mi = 0; mi < 2; mi++)
#pragma unroll
            for (int h = 0; h < 2; h++) {
                float m = -1e30f;
#pragma unroll
                for (int ni = 0; ni < 4; ni++) {
                    m = fmaxf(m, acc[mi][ni][2 * h]);
                    m = fmaxf(m, acc[mi][ni][2 * h + 1]);
                }
                m = fmaxf(m, __shfl_xor_sync(0xffffffffu, m, 1));
                m = fmaxf(m, __shfl_xor_sync(0xffffffffu, m, 2));
                tmax[mi][h] = m;
            }
        if ((lane & 3) == 0) {
#pragma unroll
            for (int mi = 0; mi < 2; mi++)
#pragma unroll
                for (int h = 0; h < 2; h++) {
                    int rl = rm + mi * 16 + gq + h * 8;
                    rS[rl * 4 + grp] = tmax[mi][h];
                }
        }
        __syncthreads();

#pragma unroll
        for (int mi = 0; mi < 2; mi++)
#pragma unroll
            for (int h = 0; h < 2; h++) {
                const int rl = rm + mi * 16 + gq + h * 8;
                float tm = fmaxf(fmaxf(rS[rl * 4], rS[rl * 4 + 1]),
                                 fmaxf(rS[rl * 4 + 2], rS[rl * 4 + 3]));
                float m_old = m_run[mi][h];
                float m_new = fmaxf(m_old, tm);
                float ratio = __expf(m_old - m_new);
                if (grp == 0 && (lane & 3) == 0)
                    g_ratio[(rowbase + m0 + rl) * 16 + nt] = ratio;
                __half* prow = g_p + (rowbase + m0 + rl) * SEQ + nt * 128;
                float s = 0.f;
#pragma unroll
                for (int ni = 0; ni < 4; ni++) {
                    float p0 = __expf(acc[mi][ni][2 * h] - m_new);
                    float p1 = __expf(acc[mi][ni][2 * h + 1] - m_new);
                    s += p0 + p1;
                    *(__half2*)(prow + cn + ni * 8 + tg2) = __floats2half2_rn(p0, p1);
                }
                s_run[mi][h] = s_run[mi][h] * ratio + s;
                m_run[mi][h] = m_new;
            }

        if (nt + 2 < 16) load_g(nt & 1, nt + 2);
        CP_COMMIT();
    }

#pragma unroll
    for (int mi = 0; mi < 2; mi++)
#pragma unroll
        for (int h = 0; h < 2; h++) {
            float v = s_run[mi][h];
            v += __shfl_xor_sync(0xffffffffu, v, 1);
            v += __shfl_xor_sync(0xffffffffu, v, 2);
            s_run[mi][h] = v;
        }
    if ((lane & 3) == 0) {
#pragma unroll
        for (int mi = 0; mi < 2; mi++)
#pragma unroll
            for (int h = 0; h < 2; h++) {
                int rl = rm + mi * 16 + gq + h * 8;
                redBase[rl * 4 + grp] = s_run[mi][h];
            }
    }
    __syncthreads();
    if (grp == 0 && (lane & 3) == 0) {
#pragma unroll
        for (int mi = 0; mi < 2; mi++)
#pragma unroll
            for (int h = 0; h < 2; h++) {
                int rl = rm + mi * 16 + gq + h * 8;
                float tot = redBase[rl * 4] + redBase[rl * 4 + 1]
                          + redBase[rl * 4 + 2] + redBase[rl * 4 + 3];
                g_inv[rowbase + m0 + rl] = 1.f / tot;
            }
    }
}

// -- AV: fp16 GEMM, CTA 128x128, 1024 thr (8 warps/SMSP), warp 16x32 -------
__global__ __launch_bounds__(NT2, 1)
void av_gemm_kernel(const float* __restrict__ xres, float* __restrict__ out)
{
    extern __shared__ char smem[];
    const uint32_t sb = smem_u32(smem);
    const int tid = threadIdx.x;
    const int wid = tid >> 5;           // 0..31
    const int lane = tid & 31;
    const int m0 = blockIdx.y * 128;
    const int n0 = blockIdx.x * 128;
    const int b  = blockIdx.z;
    const int gq   = lane >> 2;
    const int tg2  = (lane & 3) * 2;
    const int rm   = (wid & 7) * 16;    // 8 m-groups of 16
    const int cn   = (wid >> 3) * 32;   // 4 n-groups of 32

    const uint32_t aoff = (uint32_t)(rm + (lane & 15)) * PITCH + (uint32_t)(lane >> 4) * 16;
    const uint32_t boff = (uint32_t)(cn + (lane & 7) + ((lane >> 4) & 1) * 8) * PITCH
                        + (uint32_t)((lane >> 3) & 1) * 16;

    const __half* Arow = g_p + (size_t)b * SEQ * SEQ + (size_t)m0 * SEQ;
    const __half* Brow = g_xt + (size_t)b * DIM * SEQ + (size_t)n0 * SEQ;
    const float* xr = xres + (size_t)b * SEQ * DIM;
    float* ob = out + (size_t)b * SEQ * DIM;

    const size_t rowglob = (size_t)b * SEQ + m0 + rm + gq;

    float acc[4][4];                    // [ni][e], warp tile 16x32
#pragma unroll
    for (int j = 0; j < 4; j++)
#pragma unroll
        for (int e = 0; e < 4; e++) acc[j][e] = 0.f;

    // loads: A 512 chunks by tid<512, B 512 chunks by tid>=512
    const int lidx = tid & 511;
    const int lrow = lidx >> 2;
    const int lcc  = (lidx & 3) * 16;
    const bool isA = tid < 512;
    auto load_stage = [&](int s, int t) {
        const int k0 = t * 32;
        char* st = smem + s * AV_STAGE;
        if (isA) {
            cp16(st + (uint32_t)lrow * PITCH + lcc,
                 (const char*)(Arow + (size_t)lrow * SEQ + k0) + lcc);
        } else {
            cp16(st + ARR_128 + (uint32_t)lrow * PITCH + lcc,
                 (const char*)(Brow + (size_t)lrow * SEQ + k0) + lcc);
        }
    };

#pragma unroll
    for (int s = 0; s < AV_STAGES; s++) { load_stage(s, s); CP_COMMIT(); }

    const int T = SEQ / 32;   // 64
    for (int t = 0; t < T; t++) {
        CP_WAIT(AV_STAGES - 1);
        __syncthreads();

        // flash rescale at each 128-k (ratio-tile) boundary
        if ((t & 3) == 0) {
            const int nt = t >> 2;
            float rr[2];
#pragma unroll
            for (int h = 0; h < 2; h++)
                rr[h] = g_ratio[(rowglob + h * 8) * 16 + nt];
#pragma unroll
            for (int ni = 0; ni < 4; ni++)
#pragma unroll
                for (int e = 0; e < 4; e++)
                    acc[ni][e] *= rr[e >> 1];
        }

        const uint32_t stA = sb + (t % AV_STAGES) * AV_STAGE;
        const uint32_t stB = stA + ARR_128;
#pragma unroll
        for (int ks = 0; ks < 32; ks += 16) {
            uint32_t a4[4], b4[4][2];
            ldsm_x4(a4, stA + aoff + ks * 2);
#pragma unroll
            for (int pr = 0; pr < 2; pr++) {
                uint32_t t4[4];
                ldsm_x4(t4, stB + boff + pr * (16 * PITCH) + ks * 2);
                b4[2 * pr][0] = t4[0]; b4[2 * pr][1] = t4[1];
                b4[2 * pr + 1][0] = t4[2]; b4[2 * pr + 1][1] = t4[3];
            }
#pragma unroll
            for (int ni = 0; ni < 4; ni++)
                mma_f16(acc[ni], a4, b4[ni]);
        }
        __syncthreads();
        if (t + AV_STAGES < T) load_stage(t % AV_STAGES, t + AV_STAGES);
        CP_COMMIT();
    }

    float invv[2];
#pragma unroll
    for (int h = 0; h < 2; h++)
        invv[h] = g_inv[rowglob + h * 8];

#pragma unroll
    for (int ni = 0; ni < 4; ni++) {
        int r0 = m0 + rm + gq;
        int c0 = n0 + cn + ni * 8 + tg2;
#pragma unroll
        for (int e = 0; e < 4; e++) {
            int r = r0 + (e >> 1) * 8;
            int c = c0 + (e & 1);
            ob[(size_t)r * DIM + c] = acc[ni][e] * invv[e >> 1]
                                    + xr[(size_t)r * DIM + c];
        }
    }
}

// ------------------------------ launcher ----------------------------------
extern "C" void kernel_launch(void* const* d_in, const int* in_sizes, int n_in,
                              void* d_out, int out_size) {
    const float* x  = (const float*)d_in[0];
    const float* Wf = (const float*)d_in[1];
    const float* bf = (const float*)d_in[2];
    const float* Wg = (const float*)d_in[3];
    const float* bg = (const float*)d_in[4];
    float* out = (float*)d_out;

    cudaFuncSetAttribute(fg_gemm_kernel,
                         cudaFuncAttributeMaxDynamicSharedMemorySize, FG_SMEM);
    cudaFuncSetAttribute(fused_attn_kernel,
                         cudaFuncAttributeMaxDynamicSharedMemorySize, FUSED_SMEM);
    cudaFuncSetAttribute(av_gemm_kernel,
                         cudaFuncAttributeMaxDynamicSharedMemorySize, AV_SMEM);

    void *xh, *xl, *wth, *wtl;
    cudaGetSymbolAddress(&xh, g_xh);
    cudaGetSymbolAddress(&xl, g_xl);
    cudaGetSymbolAddress(&wth, g_wth);
    cudaGetSymbolAddress(&wtl, g_wtl);

    {
        dim3 grid(SEQ / 32, DIM / 32, BATCH);
        prep_x_kernel<<<grid, dim3(32, 8)>>>(x);
    }
    split_w_kernel<<<(256 * DIM) / 256, 256>>>(Wf, Wg, bf, bg);

    fg_gemm_kernel<<<BN_ROWS / 128, NT, FG_SMEM>>>(
        (const __nv_bfloat16*)xh, (const __nv_bfloat16*)xl,
        (const __nv_bfloat16*)wth, (const __nv_bfloat16*)wtl);

    {
        dim3 grid(SEQ / 128, BATCH);
        fused_attn_kernel<<<grid, NT, FUSED_SMEM>>>();
    }

    {
        dim3 grid(DIM / 128, SEQ / 128, BATCH);
        av_gemm_kernel<<<grid, NT2, AV_SMEM>>>(x, out);
    }
}

// round 13
// speedup vs baseline: 1.2440x; 1.2440x over previous
#include <cuda_runtime.h>
#include <cuda_bf16.h>
#include <cuda_fp16.h>
#include <cstdint>

// ---------------------------------------------------------------------------
// SelfAttention B=8 N=2048 D=1024 ATT=128
//   FG: bf16 hi/lo 3-term split GEMM (fp32-equiv), CTA 128x256, 1 wave,
//       3-stage cp.async pipeline
//   fused attn: single-pass exact flash softmax -> P fp16 (unnormalized,
//     running max), ratio table, g_inv
//   AV: fp16 GEMM, 512 thr, CTA 128x128, warp 32x32, 4 stages (measured
//     optimum across 5 probes); flash ratio rescale + g_inv + residual.
// mma.sync + ldmatrix.x4 (tcgen05 unavailable in this harness toolchain).
// ---------------------------------------------------------------------------

#define BATCH 8
#define SEQ   2048
#define DIM   1024
#define BN_ROWS (BATCH*SEQ)

#define NT 512

#define PITCH 80
#define ARR_128 (128*PITCH)            // 10240
#define ARR_256 (256*PITCH)            // 20480
#define FG_STAGE (2*ARR_128 + 2*ARR_256)   // 61440
#define FG_STAGES 3
#define FG_SMEM  (FG_STAGES*FG_STAGE)      // 184320
#define AV_STAGE (2*ARR_128)               // 20480
#define AV_STAGES 4
#define AV_SMEM (AV_STAGES*AV_STAGE)       // 81920
#define FPITCH 272
#define FARR (128*FPITCH)                  // 34816
#define GOFF0 (2*FARR)
#define REDOFF (6*FARR)                    // 208896
#define FUSED_SMEM (REDOFF + 4096)

// ------------------------------- scratch ----------------------------------
__device__ __nv_bfloat16 g_xh[BN_ROWS * DIM];
__device__ __nv_bfloat16 g_xl[BN_ROWS * DIM];
__device__ __half        g_xt[(size_t)BATCH * DIM * SEQ];
__device__ __nv_bfloat16 g_wth[256 * DIM];
__device__ __nv_bfloat16 g_wtl[256 * DIM];
__device__ float         g_biasc[256];
__device__ __nv_bfloat16 g_fgh[BN_ROWS * 256];
__device__ __nv_bfloat16 g_fgl[BN_ROWS * 256];
__device__ __half        g_p[(size_t)BATCH * SEQ * SEQ];   // exp(s - m_running)
__device__ float         g_ratio[(size_t)BN_ROWS * 16];    // per (row, tile)
__device__ float         g_inv[BN_ROWS];                   // 1 / Z

// ------------------------------- helpers ----------------------------------
__device__ __forceinline__ uint32_t smem_u32(const void* p) {
    uint32_t a;
    asm("{ .reg .u64 t; cvta.to.shared.u64 t, %1; cvt.u32.u64 %0, t; }"
        : "=r"(a) : "l"(p));
    return a;
}
__device__ __forceinline__ void mma_bf16(float* c, const uint32_t* a, const uint32_t* b) {
    asm volatile(
        "mma.sync.aligned.m16n8k16.row.col.f32.bf16.bf16.f32 "
        "{%0,%1,%2,%3},{%4,%5,%6,%7},{%8,%9},{%0,%1,%2,%3};\n"
        : "+f"(c[0]), "+f"(c[1]), "+f"(c[2]), "+f"(c[3])
        : "r"(a[0]), "r"(a[1]), "r"(a[2]), "r"(a[3]), "r"(b[0]), "r"(b[1]));
}
__device__ __forceinline__ void mma_f16(float* c, const uint32_t* a, const uint32_t* b) {
    asm volatile(
        "mma.sync.aligned.m16n8k16.row.col.f32.f16.f16.f32 "
        "{%0,%1,%2,%3},{%4,%5,%6,%7},{%8,%9},{%0,%1,%2,%3};\n"
        : "+f"(c[0]), "+f"(c[1]), "+f"(c[2]), "+f"(c[3])
        : "r"(a[0]), "r"(a[1]), "r"(a[2]), "r"(a[3]), "r"(b[0]), "r"(b[1]));
}
__device__ __forceinline__ void ldsm_x4(uint32_t* r, uint32_t addr) {
    asm volatile("ldmatrix.sync.aligned.m8n8.x4.shared.b16 {%0,%1,%2,%3}, [%4];"
        : "=r"(r[0]), "=r"(r[1]), "=r"(r[2]), "=r"(r[3]) : "r"(addr));
}
__device__ __forceinline__ void cp16(void* dst, const void* src) {
    uint32_t d = (uint32_t)__cvta_generic_to_shared(dst);
    asm volatile("cp.async.cg.shared.global [%0], [%1], 16;" :: "r"(d), "l"(src));
}
#define CP_COMMIT() asm volatile("cp.async.commit_group;" ::: "memory")
#define CP_WAIT(n)  asm volatile("cp.async.wait_group %0;" :: "n"(n) : "memory")

__device__ __forceinline__ void split_store(float v, __nv_bfloat16* h, __nv_bfloat16* l) {
    __nv_bfloat16 hi = __float2bfloat16(v);
    *h = hi;
    *l = __float2bfloat16(v - __bfloat162float(hi));
}

// ------------------------------ prep kernels ------------------------------
__global__ void prep_x_kernel(const float* __restrict__ x) {
    __shared__ float tile[32][33];
    int b = blockIdx.z;
    int n0 = blockIdx.x * 32, d0 = blockIdx.y * 32;
    int tx = threadIdx.x, ty = threadIdx.y;
    const float* xb = x + (size_t)b * SEQ * DIM;
#pragma unroll
    for (int j = 0; j < 4; j++) {
        int n = n0 + ty + 8 * j;
        float v = xb[(size_t)n * DIM + d0 + tx];
        tile[ty + 8 * j][tx] = v;
        size_t o = ((size_t)b * SEQ + n) * DIM + d0 + tx;
        split_store(v, &g_xh[o], &g_xl[o]);
    }
    __syncthreads();
    size_t base = (size_t)b * DIM * SEQ;
#pragma unroll
    for (int j = 0; j < 4; j++) {
        float v = tile[tx][ty + 8 * j];
        g_xt[base + (size_t)(d0 + ty + 8 * j) * SEQ + n0 + tx] = __float2half(v);
    }
}

__global__ void split_w_kernel(const float* __restrict__ Wf, const float* __restrict__ Wg,
                               const float* __restrict__ bfp, const float* __restrict__ bgp) {
    int idx = blockIdx.x * blockDim.x + threadIdx.x;
    if (idx < 256) g_biasc[idx] = (idx < 128) ? bfp[idx] : bgp[idx - 128];
    if (idx >= 256 * DIM) return;
    int n = idx >> 10;
    int k = idx & 1023;
    float v = (n < 128) ? Wf[(size_t)k * 128 + n] : Wg[(size_t)k * 128 + (n - 128)];
    split_store(v, &g_wth[idx], &g_wtl[idx]);
}

// ------------- FG: bf16 split GEMM, CTA 128x256, 3-stage pipe -------------
__global__ __launch_bounds__(NT)
void fg_gemm_kernel(const __nv_bfloat16* __restrict__ Ah, const __nv_bfloat16* __restrict__ Al,
                    const __nv_bfloat16* __restrict__ Bh, const __nv_bfloat16* __restrict__ Bl)
{
    extern __shared__ char smem[];
    const uint32_t sb = smem_u32(smem);
    const int tid = threadIdx.x;
    const int wid = tid >> 5;
    const int lane = tid & 31;
    const int m0 = blockIdx.x * 128;
    const int gq   = lane >> 2;
    const int tg2  = (lane & 3) * 2;
    const int rm   = (wid & 1) * 64;
    const int cn   = (wid >> 1) * 32;

    const uint32_t aoff = (uint32_t)(rm + (lane & 15)) * PITCH + (uint32_t)(lane >> 4) * 16;
    const uint32_t boff = (uint32_t)(cn + (lane & 7) + ((lane >> 4) & 1) * 8) * PITCH
                        + (uint32_t)((lane >> 3) & 1) * 16;

    const __nv_bfloat16* Arow_h = Ah + (size_t)m0 * DIM;
    const __nv_bfloat16* Arow_l = Al + (size_t)m0 * DIM;

    const int lrow = tid >> 2;
    const int lcc  = (tid & 3) * 16;

    float acc[4][4][4];
#pragma unroll
    for (int i = 0; i < 4; i++)
#pragma unroll
        for (int j = 0; j < 4; j++)
#pragma unroll
            for (int e = 0; e < 4; e++) acc[i][j][e] = 0.f;

    auto load_stage = [&](int s, int t) {
        const int k0 = t * 32;
        char* st = smem + s * FG_STAGE;
        uint32_t doff = (uint32_t)lrow * PITCH + lcc;
        cp16(st + doff,           (const char*)(Arow_h + (size_t)lrow * DIM + k0) + lcc);
        cp16(st + ARR_128 + doff, (const char*)(Arow_l + (size_t)lrow * DIM + k0) + lcc);
#pragma unroll
        for (int i = 0; i < 2; i++) {
            int brow = lrow + i * 128;
            uint32_t bo = (uint32_t)brow * PITCH + lcc;
            cp16(st + 2 * ARR_128 + bo,
                 (const char*)(Bh + (size_t)brow * DIM + k0) + lcc);
            cp16(st + 2 * ARR_128 + ARR_256 + bo,
                 (const char*)(Bl + (size_t)brow * DIM + k0) + lcc);
        }
    };

#pragma unroll
    for (int s = 0; s < FG_STAGES; s++) { load_stage(s, s); CP_COMMIT(); }

    const int T = DIM / 32;
    for (int t = 0; t < T; t++) {
        CP_WAIT(FG_STAGES - 1);
        __syncthreads();
        const uint32_t stA = sb + (t % FG_STAGES) * FG_STAGE;
        const uint32_t stB = stA + 2 * ARR_128;
#pragma unroll
        for (int ks = 0; ks < 32; ks += 16) {
            uint32_t ah[4][4], al[4][4], bh[4][2], bl[4][2];
#pragma unroll
            for (int mi = 0; mi < 4; mi++) {
                ldsm_x4(ah[mi], stA + aoff + mi * (16 * PITCH) + ks * 2);
                ldsm_x4(al[mi], stA + ARR_128 + aoff + mi * (16 * PITCH) + ks * 2);
            }
#pragma unroll
            for (int pr = 0; pr < 2; pr++) {
                uint32_t t4[4];
                ldsm_x4(t4, stB + boff + pr * (16 * PITCH) + ks * 2);
                bh[2 * pr][0] = t4[0]; bh[2 * pr][1] = t4[1];
                bh[2 * pr + 1][0] = t4[2]; bh[2 * pr + 1][1] = t4[3];
                ldsm_x4(t4, stB + ARR_256 + boff + pr * (16 * PITCH) + ks * 2);
                bl[2 * pr][0] = t4[0]; bl[2 * pr][1] = t4[1];
                bl[2 * pr + 1][0] = t4[2]; bl[2 * pr + 1][1] = t4[3];
            }
#pragma unroll
            for (int mi = 0; mi < 4; mi++)
#pragma unroll
                for (int ni = 0; ni < 4; ni++)
                    mma_bf16(acc[mi][ni], ah[mi], bh[ni]);
#pragma unroll
            for (int mi = 0; mi < 4; mi++)
#pragma unroll
                for (int ni = 0; ni < 4; ni++)
                    mma_bf16(acc[mi][ni], ah[mi], bl[ni]);
#pragma unroll
            for (int mi = 0; mi < 4; mi++)
#pragma unroll
                for (int ni = 0; ni < 4; ni++)
                    mma_bf16(acc[mi][ni], al[mi], bh[ni]);
        }
        __syncthreads();
        if (t + FG_STAGES < T) load_stage(t % FG_STAGES, t + FG_STAGES);
        CP_COMMIT();
    }

#pragma unroll
    for (int mi = 0; mi < 4; mi++)
#pragma unroll
        for (int ni = 0; ni < 4; ni++) {
            int r0 = m0 + rm + mi * 16 + gq;
            int c0 = cn + ni * 8 + tg2;
#pragma unroll
            for (int e = 0; e < 4; e++) {
                int r = r0 + (e >> 1) * 8;
                int c = c0 + (e & 1);
                float v = acc[mi][ni][e] + g_biasc[c];
                split_store(v, &g_fgh[(size_t)r * 256 + c], &g_fgl[(size_t)r * 256 + c]);
            }
        }
}

// ------------- fused attn: single-pass flash, ratio table ------------------
__global__ __launch_bounds__(NT)
void fused_attn_kernel()
{
    extern __shared__ char smem[];
    const uint32_t sb = smem_u32(smem);
    float* redBase = (float*)(smem + REDOFF);   // 2 x 512 floats

    const int tid = threadIdx.x;
    const int wid = tid >> 5;
    const int lane = tid & 31;
    const int gq   = lane >> 2;
    const int tg2  = (lane & 3) * 2;
    const int rm   = (wid & 3) * 32;
    const int cn   = (wid >> 2) * 32;
    const int m0 = blockIdx.x * 128;
    const int b  = blockIdx.y;
    const int grp = wid >> 2;          // n-warp-group 0..3

    const uint32_t aoff = (uint32_t)(rm + (lane & 15)) * FPITCH + (uint32_t)(lane >> 4) * 16;
    const uint32_t boff = (uint32_t)(cn + (lane & 7) + ((lane >> 4) & 1) * 8) * FPITCH
                        + (uint32_t)((lane >> 3) & 1) * 16;

    const size_t rowbase = (size_t)b * SEQ;

#pragma unroll
    for (int i = 0; i < 4; i++) {
        int idx = tid + i * NT;
        int row = idx >> 4;
        int c = (idx & 15) * 16;
        char* dst = smem + row * FPITCH + c;
        cp16(dst,        (const char*)(g_fgh + (rowbase + m0 + row) * 256) + c);
        cp16(dst + FARR, (const char*)(g_fgl + (rowbase + m0 + row) * 256) + c);
    }
    auto load_g = [&](int s, int nt) {
        char* st = smem + GOFF0 + s * (2 * FARR);
#pragma unroll
        for (int i = 0; i < 4; i++) {
            int idx = tid + i * NT;
            int row = idx >> 4;
            int c = (idx & 15) * 16;
            char* dst = st + row * FPITCH + c;
            cp16(dst,        (const char*)(g_fgh + (rowbase + nt * 128 + row) * 256 + 128) + c);
            cp16(dst + FARR, (const char*)(g_fgl + (rowbase + nt * 128 + row) * 256 + 128) + c);
        }
    };

    load_g(0, 0);
    CP_COMMIT();
    load_g(1, 1);
    CP_COMMIT();

    float m_run[2][2] = {{-1e30f, -1e30f}, {-1e30f, -1e30f}};
    float s_run[2][2] = {{0.f, 0.f}, {0.f, 0.f}};

    for (int nt = 0; nt < 16; nt++) {
        CP_WAIT(1);
        __syncthreads();
        const uint32_t stG = sb + GOFF0 + (nt & 1) * (2 * FARR);
        float* rS = redBase + (nt & 1) * 512;

        float acc[2][4][4];
#pragma unroll
        for (int i = 0; i < 2; i++)
#pragma unroll
            for (int j = 0; j < 4; j++)
#pragma unroll
                for (int e = 0; e < 4; e++) acc[i][j][e] = 0.f;

#pragma unroll
        for (int ksb = 0; ksb < 8; ksb++) {
            const int ks = ksb * 16;
            uint32_t ah[2][4], al[2][4], bh[4][2], bl[4][2];
#pragma unroll
            for (int mi = 0; mi < 2; mi++) {
                ldsm_x4(ah[mi], sb + aoff + mi * (16 * FPITCH) + ks * 2);
                ldsm_x4(al[mi], sb + FARR + aoff + mi * (16 * FPITCH) + ks * 2);
            }
#pragma unroll
            for (int pr = 0; pr < 2; pr++) {
                uint32_t t4[4];
                ldsm_x4(t4, stG + boff + pr * (16 * FPITCH) + ks * 2);
                bh[2 * pr][0] = t4[0]; bh[2 * pr][1] = t4[1];
                bh[2 * pr + 1][0] = t4[2]; bh[2 * pr + 1][1] = t4[3];
                ldsm_x4(t4, stG + FARR + boff + pr * (16 * FPITCH) + ks * 2);
                bl[2 * pr][0] = t4[0]; bl[2 * pr][1] = t4[1];
                bl[2 * pr + 1][0] = t4[2]; bl[2 * pr + 1][1] = t4[3];
            }
#pragma unroll
            for (int mi = 0; mi < 2; mi++)
#pragma unroll
                for (int ni = 0; ni < 4; ni++)
                    mma_bf16(acc[mi][ni], ah[mi], bh[ni]);
#pragma unroll
            for (int mi = 0; mi < 2; mi++)
#pragma unroll
                for (int ni = 0; ni < 4; ni++)
                    mma_bf16(acc[mi][ni], ah[mi], bl[ni]);
#pragma unroll
            for (int mi = 0; mi < 2; mi++)
#pragma unroll
                for (int ni = 0; ni < 4; ni++)
                    mma_bf16(acc[mi][ni], al[mi], bh[ni]);
        }

        float tmax[2][2];
#pragma unroll
        for (int mi = 0; mi < 2; mi++)
#pragma unroll
            for (int h = 0; h < 2; h++) {
                float m = -1e30f;
#pragma unroll
                for (int ni = 0; ni < 4; ni++) {
                    m = fmaxf(m, acc[mi][ni][2 * h]);
                    m = fmaxf(m, acc[mi][ni][2 * h + 1]);
                }
                m = fmaxf(m, __shfl_xor_sync(0xffffffffu, m, 1));
                m = fmaxf(m, __shfl_xor_sync(0xffffffffu, m, 2));
                tmax[mi][h] = m;
            }
        if ((lane & 3) == 0) {
#pragma unroll
            for (int mi = 0; mi < 2; mi++)
#pragma unroll
                for (int h = 0; h < 2; h++) {
                    int rl = rm + mi * 16 + gq + h * 8;
                    rS[rl * 4 + grp] = tmax[mi][h];
                }
        }
        __syncthreads();

#pragma unroll
        for (int mi = 0; mi < 2; mi++)
#pragma unroll
            for (int h = 0; h < 2; h++) {
                const int rl = rm + mi * 16 + gq + h * 8;
                float tm = fmaxf(fmaxf(rS[rl * 4], rS[rl * 4 + 1]),
                                 fmaxf(rS[rl * 4 + 2], rS[rl * 4 + 3]));
                float m_old = m_run[mi][h];
                float m_new = fmaxf(m_old, tm);
                float ratio = __expf(m_old - m_new);
                if (grp == 0 && (lane & 3) == 0)
                    g_ratio[(rowbase + m0 + rl) * 16 + nt] = ratio;
                __half* prow = g_p + (rowbase + m0 + rl) * SEQ + nt * 128;
                float s = 0.f;
#pragma unroll
                for (int ni = 0; ni < 4; ni++) {
                    float p0 = __expf(acc[mi][ni][2 * h] - m_new);
                    float p1 = __expf(acc[mi][ni][2 * h + 1] - m_new);
                    s += p0 + p1;
                    *(__half2*)(prow + cn + ni * 8 + tg2) = __floats2half2_rn(p0, p1);
                }
                s_run[mi][h] = s_run[mi][h] * ratio + s;
                m_run[mi][h] = m_new;
            }

        if (nt + 2 < 16) load_g(nt & 1, nt + 2);
        CP_COMMIT();
    }

#pragma unroll
    for (int mi = 0; mi < 2; mi++)
#pragma unroll
        for (int h = 0; h < 2; h++) {
            float v = s_run[mi][h];
            v += __shfl_xor_sync(0xffffffffu, v, 1);
            v += __shfl_xor_sync(0xffffffffu, v, 2);
            s_run[mi][h] = v;
        }
    if ((lane & 3) == 0) {
#pragma unroll
        for (int mi = 0; mi < 2; mi++)
#pragma unroll
            for (int h = 0; h < 2; h++) {
                int rl = rm + mi * 16 + gq + h * 8;
                redBase[rl * 4 + grp] = s_run[mi][h];
            }
    }
    __syncthreads();
    if (grp == 0 && (lane & 3) == 0) {
#pragma unroll
        for (int mi = 0; mi < 2; mi++)
#pragma unroll
            for (int h = 0; h < 2; h++) {
                int rl = rm + mi * 16 + gq + h * 8;
                float tot = redBase[rl * 4] + redBase[rl * 4 + 1]
                          + redBase[rl * 4 + 2] + redBase[rl * 4 + 3];
                g_inv[rowbase + m0 + rl] = 1.f / tot;
            }
    }
}

// ---- AV: fp16 GEMM, 512 thr, CTA 128x128, 4 stages, flash rescale --------
__global__ __launch_bounds__(NT)
void av_gemm_kernel(const float* __restrict__ xres, float* __restrict__ out)
{
    extern __shared__ char smem[];
    const uint32_t sb = smem_u32(smem);
    const int tid = threadIdx.x;
    const int wid = tid >> 5;
    const int lane = tid & 31;
    const int m0 = blockIdx.y * 128;
    const int n0 = blockIdx.x * 128;
    const int b  = blockIdx.z;
    const int gq   = lane >> 2;
    const int tg2  = (lane & 3) * 2;
    const int rm   = (wid & 3) * 32;
    const int cn   = (wid >> 2) * 32;

    const uint32_t aoff = (uint32_t)(rm + (lane & 15)) * PITCH + (uint32_t)(lane >> 4) * 16;
    const uint32_t boff = (uint32_t)(cn + (lane & 7) + ((lane >> 4) & 1) * 8) * PITCH
                        + (uint32_t)((lane >> 3) & 1) * 16;

    const __half* Arow = g_p + (size_t)b * SEQ * SEQ + (size_t)m0 * SEQ;
    const __half* Brow = g_xt + (size_t)b * DIM * SEQ + (size_t)n0 * SEQ;
    const float* xr = xres + (size_t)b * SEQ * DIM;
    float* ob = out + (size_t)b * SEQ * DIM;

    const size_t rowglob = (size_t)b * SEQ + m0 + rm + gq;

    const int lrow = tid >> 2;
    const int lcc  = (tid & 3) * 16;

    float acc[2][4][4];
#pragma unroll
    for (int i = 0; i < 2; i++)
#pragma unroll
        for (int j = 0; j < 4; j++)
#pragma unroll
            for (int e = 0; e < 4; e++) acc[i][j][e] = 0.f;

    auto load_stage = [&](int s, int t) {
        const int k0 = t * 32;
        char* st = smem + s * AV_STAGE;
        uint32_t doff = (uint32_t)lrow * PITCH + lcc;
        cp16(st + doff,           (const char*)(Arow + (size_t)lrow * SEQ + k0) + lcc);
        cp16(st + ARR_128 + doff, (const char*)(Brow + (size_t)lrow * SEQ + k0) + lcc);
    };

#pragma unroll
    for (int s = 0; s < AV_STAGES; s++) { load_stage(s, s); CP_COMMIT(); }

    const int T = SEQ / 32;   // 64
    for (int t = 0; t < T; t++) {
        CP_WAIT(AV_STAGES - 1);
        __syncthreads();

        if ((t & 3) == 0) {
            const int nt = t >> 2;
            float rr[2][2];
#pragma unroll
            for (int mi = 0; mi < 2; mi++)
#pragma unroll
                for (int h = 0; h < 2; h++)
                    rr[mi][h] = g_ratio[(rowglob + mi * 16 + h * 8) * 16 + nt];
#pragma unroll
            for (int mi = 0; mi < 2; mi++)
#pragma unroll
                for (int ni = 0; ni < 4; ni++)
#pragma unroll
                    for (int e = 0; e < 4; e++)
                        acc[mi][ni][e] *= rr[mi][e >> 1];
        }

        const uint32_t stA = sb + (t % AV_STAGES) * AV_STAGE;
        const uint32_t stB = stA + ARR_128;
#pragma unroll
        for (int ks = 0; ks < 32; ks += 16) {
            uint32_t a4[2][4], b4[4][2];
#pragma unroll
            for (int mi = 0; mi < 2; mi++)
                ldsm_x4(a4[mi], stA + aoff + mi * (16 * PITCH) + ks * 2);
#pragma unroll
            for (int pr = 0; pr < 2; pr++) {
                uint32_t t4[4];
                ldsm_x4(t4, stB + boff + pr * (16 * PITCH) + ks * 2);
                b4[2 * pr][0] = t4[0]; b4[2 * pr][1] = t4[1];
                b4[2 * pr + 1][0] = t4[2]; b4[2 * pr + 1][1] = t4[3];
            }
#pragma unroll
            for (int mi = 0; mi < 2; mi++)
#pragma unroll
                for (int ni = 0; ni < 4; ni++)
                    mma_f16(acc[mi][ni], a4[mi], b4[ni]);
        }
        __syncthreads();
        if (t + AV_STAGES < T) load_stage(t % AV_STAGES, t + AV_STAGES);
        CP_COMMIT();
    }

    float invv[2][2];
#pragma unroll
    for (int mi = 0; mi < 2; mi++)
#pragma unroll
        for (int h = 0; h < 2; h++)
            invv[mi][h] = g_inv[rowglob + mi * 16 + h * 8];

#pragma unroll
    for (int mi = 0; mi < 2; mi++)
#pragma unroll
        for (int ni = 0; ni < 4; ni++) {
            int r0 = m0 + rm + mi * 16 + gq;
            int c0 = n0 + cn + ni * 8 + tg2;
#pragma unroll
            for (int e = 0; e < 4; e++) {
                int r = r0 + (e >> 1) * 8;
                int c = c0 + (e & 1);
                ob[(size_t)r * DIM + c] = acc[mi][ni][e] * invv[mi][e >> 1]
                                        + xr[(size_t)r * DIM + c];
            }
        }
}

// ------------------------------ launcher ----------------------------------
extern "C" void kernel_launch(void* const* d_in, const int* in_sizes, int n_in,
                              void* d_out, int out_size) {
    const float* x  = (const float*)d_in[0];
    const float* Wf = (const float*)d_in[1];
    const float* bf = (const float*)d_in[2];
    const float* Wg = (const float*)d_in[3];
    const float* bg = (const float*)d_in[4];
    float* out = (float*)d_out;

    cudaFuncSetAttribute(fg_gemm_kernel,
                         cudaFuncAttributeMaxDynamicSharedMemorySize, FG_SMEM);
    cudaFuncSetAttribute(fused_attn_kernel,
                         cudaFuncAttributeMaxDynamicSharedMemorySize, FUSED_SMEM);
    cudaFuncSetAttribute(av_gemm_kernel,
                         cudaFuncAttributeMaxDynamicSharedMemorySize, AV_SMEM);

    void *xh, *xl, *wth, *wtl;
    cudaGetSymbolAddress(&xh, g_xh);
    cudaGetSymbolAddress(&xl, g_xl);
    cudaGetSymbolAddress(&wth, g_wth);
    cudaGetSymbolAddress(&wtl, g_wtl);

    {
        dim3 grid(SEQ / 32, DIM / 32, BATCH);
        prep_x_kernel<<<grid, dim3(32, 8)>>>(x);
    }
    split_w_kernel<<<(256 * DIM) / 256, 256>>>(Wf, Wg, bf, bg);

    fg_gemm_kernel<<<BN_ROWS / 128, NT, FG_SMEM>>>(
        (const __nv_bfloat16*)xh, (const __nv_bfloat16*)xl,
        (const __nv_bfloat16*)wth, (const __nv_bfloat16*)wtl);

    {
        dim3 grid(SEQ / 128, BATCH);
        fused_attn_kernel<<<grid, NT, FUSED_SMEM>>>();
    }

    {
        dim3 grid(DIM / 128, SEQ / 128, BATCH);
        av_gemm_kernel<<<grid, NT, AV_SMEM>>>(x, out);
    }
}